// round 7
// baseline (speedup 1.0000x reference)
#include <cuda_runtime.h>
#include <cuda_fp16.h>
#include <cstdint>

#define BB   64
#define TT   200
#define INF  512
#define HID  1024
#define OUTF 512
#define DELAYS 20
#define BH   (BB * HID)          // 65536
#define NBLK (TT / DELAYS)       // 10
#define MBLK (DELAYS * BB)       // 1280 rows per time-block
#define STG  3

// ---------------- scratch (device globals) ----------------------------------
__device__ __half g_xh[(size_t)TT * BB * INF];
__device__ __half g_Win[(size_t)INF * HID];
__device__ __half g_Wlat[(size_t)HID * HID];
__device__ __half g_WoutT[(size_t)HID * OUTF];
__device__ float  g_syn[(size_t)TT * BH];
__device__ __half g_firing[(size_t)TT * BH];
__device__ float  g_volt[BH];
__device__ float  g_asc[2 * BH];
__device__ float  g_fire[BH];

// ---------------- streams / events -------------------------------------------
struct Ctx {
    cudaStream_t s1, s2;
    cudaEvent_t e_fork, e_wlat, e_trans;
    Ctx() {
        cudaStreamCreateWithFlags(&s1, cudaStreamNonBlocking);
        cudaStreamCreateWithFlags(&s2, cudaStreamNonBlocking);
        cudaEventCreateWithFlags(&e_fork,  cudaEventDisableTiming);
        cudaEventCreateWithFlags(&e_wlat,  cudaEventDisableTiming);
        cudaEventCreateWithFlags(&e_trans, cudaEventDisableTiming);
    }
};
static Ctx g_ctx;

// ---------------- PTX helpers ------------------------------------------------
__device__ __forceinline__ void cp16(void* dst, const void* src) {
    uint32_t d = (uint32_t)__cvta_generic_to_shared(dst);
    asm volatile("cp.async.cg.shared.global [%0], [%1], 16;\n" :: "r"(d), "l"(src));
}
__device__ __forceinline__ void cp_commit() { asm volatile("cp.async.commit_group;\n"); }
__device__ __forceinline__ void cp_wait1()  { asm volatile("cp.async.wait_group 1;\n"); }

__device__ __forceinline__ void ldmx4(uint32_t* r, uint32_t addr) {
    asm volatile("ldmatrix.sync.aligned.m8n8.x4.shared.b16 {%0,%1,%2,%3}, [%4];\n"
                 : "=r"(r[0]), "=r"(r[1]), "=r"(r[2]), "=r"(r[3]) : "r"(addr));
}
__device__ __forceinline__ void ldmx4t(uint32_t* r, uint32_t addr) {
    asm volatile("ldmatrix.sync.aligned.m8n8.x4.trans.shared.b16 {%0,%1,%2,%3}, [%4];\n"
                 : "=r"(r[0]), "=r"(r[1]), "=r"(r[2]), "=r"(r[3]) : "r"(addr));
}
__device__ __forceinline__ void mma16816(float* c, const uint32_t* a, const uint32_t* b) {
    asm volatile(
        "mma.sync.aligned.m16n8k16.row.col.f32.f16.f16.f32 "
        "{%0,%1,%2,%3}, {%4,%5,%6,%7}, {%8,%9}, {%0,%1,%2,%3};\n"
        : "+f"(c[0]), "+f"(c[1]), "+f"(c[2]), "+f"(c[3])
        : "r"(a[0]), "r"(a[1]), "r"(a[2]), "r"(a[3]), "r"(b[0]), "r"(b[1]));
}

// ---------------- mma.sync GEMM, 512 threads, 128x128 tile, BK=64 ------------
// MODE 0: plain store   1: C += acc   2: bias + permuted store to [B][T][OUT]
template<int BM, int BN, int WM, int WN, int MODE>
__global__ __launch_bounds__(WM * WN * 32, 1) void mgemm(
    const __half* __restrict__ A, const __half* __restrict__ Bm,
    float* __restrict__ C, const float* __restrict__ bias,
    int M, int N, int K, int moff)
{
    constexpr int THREADS = WM * WN * 32;
    constexpr int RPW = BM / WM;        // 32
    constexpr int CPW = BN / WN;        // 32
    constexpr int MF  = RPW / 16;       // 2
    constexpr int NF  = CPW / 8;        // 4

    extern __shared__ __half smem[];
    __half* sA = smem;                    // [STG][BM*64]
    __half* sB = smem + STG * BM * 64;    // [STG][64*BN]

    const int tid  = threadIdx.x;
    const int l    = tid & 31;
    const int warp = tid >> 5;
    const int wm   = (warp / WN) * RPW;
    const int wn   = (warp % WN) * CPW;
    const int bm   = blockIdx.y * BM;
    const int bn   = blockIdx.x * BN;

    float acc[MF][NF][4] = {};
    const int KT = K >> 6;

    auto load_stage = [&](int kt, int st) {
        const int k0 = kt << 6;
        constexpr int GA = BM * 8 / THREADS;
#pragma unroll
        for (int i = 0; i < GA; i++) {
            int c = tid + i * THREADS;
            int row = c >> 3, g = c & 7;
            cp16(sA + st * BM * 64 + row * 64 + ((g ^ (row & 7)) << 3),
                 A + (size_t)(bm + row) * K + k0 + (g << 3));
        }
        constexpr int GB = 8 * BN / THREADS;
#pragma unroll
        for (int i = 0; i < GB; i++) {
            int c = tid + i * THREADS;
            int k = c / (BN / 8), g = c % (BN / 8);
            int blk = g >> 3, gg = (g & 7) ^ (k & 7);
            cp16(sB + st * 64 * BN + k * BN + blk * 64 + (gg << 3),
                 Bm + (size_t)(k0 + k) * N + bn + (g << 3));
        }
    };

    load_stage(0, 0); cp_commit();
    load_stage(1, 1); cp_commit();

    for (int kt = 0; kt < KT; kt++) {
        const int st = kt % STG;
        cp_wait1();
        __syncthreads();
        if (kt + 2 < KT) load_stage(kt + 2, (kt + 2) % STG);
        cp_commit();

        uint32_t baseA = (uint32_t)__cvta_generic_to_shared(sA + st * BM * 64);
        uint32_t baseB = (uint32_t)__cvta_generic_to_shared(sB + st * 64 * BN);

#pragma unroll
        for (int kk = 0; kk < 4; kk++) {
            uint32_t a[MF][4];
#pragma unroll
            for (int i = 0; i < MF; i++) {
                int row = wm + i * 16 + (l & 15);
                int g   = kk * 2 + (l >> 4);
                ldmx4(a[i], baseA + (uint32_t)(row * 64 + ((g ^ (row & 7)) << 3)) * 2);
            }
            uint32_t b[NF / 2][4];
#pragma unroll
            for (int j = 0; j < NF / 2; j++) {
                int k = kk * 16 + (l & 15);
                int g = ((wn + j * 16) >> 3) + (l >> 4);
                int blk = g >> 3, gg = (g & 7) ^ (k & 7);
                ldmx4t(b[j], baseB + (uint32_t)(k * BN + blk * 64 + (gg << 3)) * 2);
            }
#pragma unroll
            for (int i = 0; i < MF; i++)
#pragma unroll
                for (int j = 0; j < NF / 2; j++) {
                    mma16816(acc[i][2 * j],     a[i], b[j]);
                    mma16816(acc[i][2 * j + 1], a[i], b[j] + 2);
                }
        }
    }

    // ---- epilogue ----
    const int r  = l >> 2;
    const int c0 = (l & 3) * 2;
#pragma unroll
    for (int i = 0; i < MF; i++) {
        int m0 = bm + wm + i * 16;
#pragma unroll
        for (int j = 0; j < NF; j++) {
            int col = bn + wn + j * 8 + c0;
#pragma unroll
            for (int h = 0; h < 2; h++) {
                int m = m0 + r + h * 8;
                float2 val = make_float2(acc[i][j][2 * h], acc[i][j][2 * h + 1]);
                if (MODE == 0) {
                    *reinterpret_cast<float2*>(&C[(size_t)m * N + col]) = val;
                } else if (MODE == 1) {
                    float2* p = reinterpret_cast<float2*>(&C[(size_t)m * N + col]);
                    float2 o = *p;
                    o.x += val.x; o.y += val.y;
                    *p = o;
                } else {
                    float2 bb = *reinterpret_cast<const float2*>(&bias[col]);
                    val.x += bb.x; val.y += bb.y;
                    int mg = moff + m;
                    int t = mg >> 6, b0 = mg & 63;
                    *reinterpret_cast<float2*>(
                        &C[((size_t)b0 * TT + t) * OUTF + col]) = val;
                }
            }
        }
    }
}

// ---------------- conversion kernels -----------------------------------------
__global__ __launch_bounds__(256) void convx_kernel(const float* __restrict__ x,
                                                    __half* __restrict__ xh)
{
    int i  = blockIdx.x * 256 + threadIdx.x;
    int i4 = i % (INF / 4);
    int bt = i / (INF / 4);
    int b = bt / TT, t = bt % TT;
    float4 v = reinterpret_cast<const float4*>(x)[i];
    int dst = (t * BB + b) * (INF / 4) + i4;
    reinterpret_cast<__half2*>(xh)[2 * dst + 0] = __floats2half2_rn(v.x, v.y);
    reinterpret_cast<__half2*>(xh)[2 * dst + 1] = __floats2half2_rn(v.z, v.w);
}

__global__ __launch_bounds__(256) void f2h_kernel(const float* __restrict__ in,
                                                  __half* __restrict__ out)
{
    int i = blockIdx.x * 256 + threadIdx.x;
    float4 v = reinterpret_cast<const float4*>(in)[i];
    reinterpret_cast<__half2*>(out)[2 * i + 0] = __floats2half2_rn(v.x, v.y);
    reinterpret_cast<__half2*>(out)[2 * i + 1] = __floats2half2_rn(v.z, v.w);
}

__global__ void transp_kernel(const float* __restrict__ w, __half* __restrict__ wt)
{
    __shared__ float tile[32][33];
    int ox = blockIdx.x * 32, hy = blockIdx.y * 32;
    int tx = threadIdx.x, ty = threadIdx.y;
#pragma unroll
    for (int rr = 0; rr < 32; rr += 8)
        tile[ty + rr][tx] = w[(size_t)(ox + ty + rr) * HID + hy + tx];
    __syncthreads();
#pragma unroll
    for (int rr = 0; rr < 32; rr += 8)
        wt[(size_t)(hy + ty + rr) * OUTF + ox + tx] = __float2half(tile[tx][ty + rr]);
}

// ---------------- elementwise 20-step scan, 2 lanes per thread ----------------
__device__ __forceinline__ float sigm(float x) { return 1.0f / (1.0f + __expf(-x)); }

__global__ __launch_bounds__(128) void scan_kernel(
    const float* __restrict__ syn_all,
    const float* __restrict__ trans_k_m,
    const float* __restrict__ trans_asc_k,
    const float* __restrict__ asc_amp,
    const float* __restrict__ trans_asc_r,
    const float* __restrict__ thresh,
    __half* __restrict__ firing,
    float* __restrict__ volt_st, float* __restrict__ asc_st,
    float* __restrict__ fire_st, int t0)
{
    int p   = blockIdx.x * blockDim.x + threadIdx.x;  // pair index over BH/2
    int idx = p * 2;
    int h   = idx & (HID - 1);

    float2 syn[DELAYS];
#pragma unroll
    for (int s = 0; s < DELAYS; s++)
        syn[s] = *reinterpret_cast<const float2*>(&syn_all[(size_t)(t0 + s) * BH + idx]);

    float2 tkm  = *reinterpret_cast<const float2*>(&trans_k_m[h]);
    float2 tk0  = *reinterpret_cast<const float2*>(&trans_asc_k[h]);
    float2 tk1  = *reinterpret_cast<const float2*>(&trans_asc_k[HID + h]);
    float2 am0  = *reinterpret_cast<const float2*>(&asc_amp[h]);
    float2 am1  = *reinterpret_cast<const float2*>(&asc_amp[HID + h]);
    float2 tr0  = *reinterpret_cast<const float2*>(&trans_asc_r[h]);
    float2 tr1  = *reinterpret_cast<const float2*>(&trans_asc_r[HID + h]);
    float2 thv  = *reinterpret_cast<const float2*>(&thresh[h]);

    float kmx = sigm(tkm.x), kmy = sigm(tkm.y);
    float c1x = 0.1f * kmx,  c1y = 0.1f * kmy;
    float c2x = 1.f - kmx,   c2y = 1.f - kmy;
    float ka0x = sigm(tk0.x), ka0y = sigm(tk0.y);
    float ka1x = sigm(tk1.x), ka1y = sigm(tk1.y);
    float r0x = 1.f - 2.f * sigm(tr0.x), r0y = 1.f - 2.f * sigm(tr0.y);
    float r1x = 1.f - 2.f * sigm(tr1.x), r1y = 1.f - 2.f * sigm(tr1.y);

    float fx, fy, vx, vy, a0x, a0y, a1x, a1y;
    if (t0 == 0) {
        fx = fy = vx = vy = a0x = a0y = a1x = a1y = 0.f;
    } else {
        float2 t;
        t = *reinterpret_cast<const float2*>(&fire_st[idx]); fx = t.x; fy = t.y;
        t = *reinterpret_cast<const float2*>(&volt_st[idx]); vx = t.x; vy = t.y;
        t = *reinterpret_cast<const float2*>(&asc_st[idx]);  a0x = t.x; a0y = t.y;
        t = *reinterpret_cast<const float2*>(&asc_st[BH + idx]); a1x = t.x; a1y = t.y;
    }

#pragma unroll
    for (int s = 0; s < DELAYS; s++) {
        a0x = (am0.x + r0x * a0x) * fx * ka0x + (1.f - ka0x) * a0x;
        a0y = (am0.y + r0y * a0y) * fy * ka0y + (1.f - ka0y) * a0y;
        a1x = (am1.x + r1x * a1x) * fx * ka1x + (1.f - ka1x) * a1x;
        a1y = (am1.y + r1y * a1y) * fy * ka1y + (1.f - ka1y) * a1y;
        vx = c1x * (syn[s].x + a0x + a1x) + c2x * vx;
        vy = c1y * (syn[s].y + a0y + a1y) + c2y * vy;
        fx = sigm(vx - thv.x);
        fy = sigm(vy - thv.y);
        *reinterpret_cast<__half2*>(&firing[(size_t)(t0 + s) * BH + idx]) =
            __floats2half2_rn(fx, fy);
    }
    *reinterpret_cast<float2*>(&fire_st[idx]) = make_float2(fx, fy);
    *reinterpret_cast<float2*>(&volt_st[idx]) = make_float2(vx, vy);
    *reinterpret_cast<float2*>(&asc_st[idx])  = make_float2(a0x, a0y);
    *reinterpret_cast<float2*>(&asc_st[BH + idx]) = make_float2(a1x, a1y);
}

// ---------------- launch ------------------------------------------------------
extern "C" void kernel_launch(void* const* d_in, const int* in_sizes, int n_in,
                              void* d_out, int out_size)
{
    const float* x           = (const float*)d_in[0];
    const float* W_in        = (const float*)d_in[1];
    const float* W_lat       = (const float*)d_in[2];
    const float* thresh      = (const float*)d_in[3];
    const float* trans_k_m   = (const float*)d_in[4];
    const float* trans_asc_k = (const float*)d_in[5];
    const float* asc_amp     = (const float*)d_in[6];
    const float* trans_asc_r = (const float*)d_in[7];
    const float* W_out       = (const float*)d_in[8];
    const float* b_out       = (const float*)d_in[9];
    float* out = (float*)d_out;

    __half *xh, *Win, *Wlat, *WoutT, *firing;
    float *syn, *volt, *asc, *fire;
    cudaGetSymbolAddress((void**)&xh,     g_xh);
    cudaGetSymbolAddress((void**)&Win,    g_Win);
    cudaGetSymbolAddress((void**)&Wlat,   g_Wlat);
    cudaGetSymbolAddress((void**)&WoutT,  g_WoutT);
    cudaGetSymbolAddress((void**)&syn,    g_syn);
    cudaGetSymbolAddress((void**)&firing, g_firing);
    cudaGetSymbolAddress((void**)&volt,   g_volt);
    cudaGetSymbolAddress((void**)&asc,    g_asc);
    cudaGetSymbolAddress((void**)&fire,   g_fire);

    const int SM_BIG = STG * (128 * 64 + 64 * 128) * 2;   // 98304
    cudaFuncSetAttribute(mgemm<128, 128, 4, 4, 0>,
                         cudaFuncAttributeMaxDynamicSharedMemorySize, SM_BIG);
    cudaFuncSetAttribute(mgemm<128, 128, 4, 4, 1>,
                         cudaFuncAttributeMaxDynamicSharedMemorySize, SM_BIG);
    cudaFuncSetAttribute(mgemm<128, 128, 4, 4, 2>,
                         cudaFuncAttributeMaxDynamicSharedMemorySize, SM_BIG);

    cudaStream_t s0 = 0, s1 = g_ctx.s1, s2 = g_ctx.s2;

    // ---- fork event FIRST (capture-legal fork of side streams) ----
    cudaEventRecord(g_ctx.e_fork, s0);

    // ---- s1: W_lat fp16 conversion (tiny; done before first lateral) ----
    cudaStreamWaitEvent(s1, g_ctx.e_fork, 0);
    f2h_kernel<<<(HID * HID / 4) / 256, 256, 0, s1>>>(W_lat, Wlat);
    cudaEventRecord(g_ctx.e_wlat, s1);

    // ---- s2: W_out transpose (tiny; done before readout) ----
    cudaStreamWaitEvent(s2, g_ctx.e_fork, 0);
    transp_kernel<<<dim3(OUTF / 32, HID / 32), dim3(32, 8), 0, s2>>>(W_out, WoutT);
    cudaEventRecord(g_ctx.e_trans, s2);

    // ---- main stream: everything heavy, strictly sequential ----
    convx_kernel<<<(BB * TT * INF / 4) / 256, 256, 0, s0>>>(x, xh);
    f2h_kernel<<<(INF * HID / 4) / 256, 256, 0, s0>>>(W_in, Win);
    mgemm<128, 128, 4, 4, 0><<<dim3(HID / 128, (BB * TT) / 128), 512, SM_BIG, s0>>>(
        xh, Win, syn, nullptr, BB * TT, HID, INF, 0);
    cudaStreamWaitEvent(s0, g_ctx.e_wlat, 0);

    for (int blk = 0; blk < NBLK; blk++) {
        if (blk > 0) {
            mgemm<128, 128, 4, 4, 1><<<dim3(HID / 128, MBLK / 128), 512, SM_BIG, s0>>>(
                firing + (size_t)(blk - 1) * MBLK * HID, Wlat,
                syn + (size_t)blk * MBLK * HID, nullptr, MBLK, HID, HID, 0);
        }
        scan_kernel<<<(BH / 2) / 128, 128, 0, s0>>>(
            syn, trans_k_m, trans_asc_k, asc_amp, trans_asc_r, thresh,
            firing, volt, asc, fire, blk * DELAYS);
    }

    // ---- readout: single full GEMM with fused bias + permute ----
    cudaStreamWaitEvent(s0, g_ctx.e_trans, 0);
    mgemm<128, 128, 4, 4, 2><<<dim3(OUTF / 128, (BB * TT) / 128), 512, SM_BIG, s0>>>(
        firing, WoutT, out, b_out, BB * TT, OUTF, HID, 0);
}

// round 10
// speedup vs baseline: 1.1476x; 1.1476x over previous
#include <cuda_runtime.h>
#include <cuda_fp16.h>
#include <cstdint>

#define BB   64
#define TT   200
#define INF  512
#define HID  1024
#define OUTF 512
#define DELAYS 20
#define BH   (BB * HID)          // 65536
#define NBLK (TT / DELAYS)       // 10
#define MBLK (DELAYS * BB)       // 1280
#define STG  3

// ---------------- scratch (device globals) ----------------------------------
__device__ __half g_xh[(size_t)TT * BB * INF];
__device__ __half g_Win[(size_t)INF * HID];
__device__ __half g_Wlat[(size_t)HID * HID];
__device__ __half g_WoutT[(size_t)HID * OUTF];
__device__ float  g_syn[(size_t)TT * BH];
__device__ __half g_firing[(size_t)TT * BH];
__device__ float  g_volt[BH];
__device__ float  g_asc[2 * BH];
__device__ float  g_fire[BH];

// ---------------- streams / events -------------------------------------------
struct Ctx {
    cudaStream_t s1, s2;
    cudaEvent_t e_fork, e_wlat, e_trans;
    Ctx() {
        cudaStreamCreateWithFlags(&s1, cudaStreamNonBlocking);
        cudaStreamCreateWithFlags(&s2, cudaStreamNonBlocking);
        cudaEventCreateWithFlags(&e_fork,  cudaEventDisableTiming);
        cudaEventCreateWithFlags(&e_wlat,  cudaEventDisableTiming);
        cudaEventCreateWithFlags(&e_trans, cudaEventDisableTiming);
    }
};
static Ctx g_ctx;

// ---------------- PTX helpers ------------------------------------------------
__device__ __forceinline__ void cp16(void* dst, const void* src) {
    uint32_t d = (uint32_t)__cvta_generic_to_shared(dst);
    asm volatile("cp.async.cg.shared.global [%0], [%1], 16;\n" :: "r"(d), "l"(src));
}
__device__ __forceinline__ void cp_commit() { asm volatile("cp.async.commit_group;\n"); }
__device__ __forceinline__ void cp_wait1()  { asm volatile("cp.async.wait_group 1;\n"); }

__device__ __forceinline__ void ldmx4(uint32_t* r, uint32_t addr) {
    asm volatile("ldmatrix.sync.aligned.m8n8.x4.shared.b16 {%0,%1,%2,%3}, [%4];\n"
                 : "=r"(r[0]), "=r"(r[1]), "=r"(r[2]), "=r"(r[3]) : "r"(addr));
}
__device__ __forceinline__ void ldmx4t(uint32_t* r, uint32_t addr) {
    asm volatile("ldmatrix.sync.aligned.m8n8.x4.trans.shared.b16 {%0,%1,%2,%3}, [%4];\n"
                 : "=r"(r[0]), "=r"(r[1]), "=r"(r[2]), "=r"(r[3]) : "r"(addr));
}
__device__ __forceinline__ void mma16816(float* c, const uint32_t* a, const uint32_t* b) {
    asm volatile(
        "mma.sync.aligned.m16n8k16.row.col.f32.f16.f16.f32 "
        "{%0,%1,%2,%3}, {%4,%5,%6,%7}, {%8,%9}, {%0,%1,%2,%3};\n"
        : "+f"(c[0]), "+f"(c[1]), "+f"(c[2]), "+f"(c[3])
        : "r"(a[0]), "r"(a[1]), "r"(a[2]), "r"(a[3]), "r"(b[0]), "r"(b[1]));
}

// ---------------- mma.sync GEMM (exact R3 configuration) ---------------------
// BK = 64 halves, SW128 xor swizzle, 3-stage cp.async pipeline
// MODE 0: plain store   1: C += acc   2: bias + permuted store to [B][T][OUT]
template<int BM, int BN, int WM, int WN, int MODE>
__global__ __launch_bounds__(WM * WN * 32, MODE == 1 ? 4 : 2) void mgemm(
    const __half* __restrict__ A, const __half* __restrict__ Bm,
    float* __restrict__ C, const float* __restrict__ bias,
    int M, int N, int K)
{
    constexpr int THREADS = WM * WN * 32;
    constexpr int RPW = BM / WM;
    constexpr int CPW = BN / WN;
    constexpr int MF  = RPW / 16;
    constexpr int NF  = CPW / 8;

    extern __shared__ __half smem[];
    __half* sA = smem;                    // [STG][BM*64]
    __half* sB = smem + STG * BM * 64;    // [STG][64*BN]

    const int tid  = threadIdx.x;
    const int l    = tid & 31;
    const int warp = tid >> 5;
    const int wm   = (warp / WN) * RPW;
    const int wn   = (warp % WN) * CPW;
    const int bm   = blockIdx.y * BM;
    const int bn   = blockIdx.x * BN;

    float acc[MF][NF][4] = {};
    const int KT = K >> 6;

    auto load_stage = [&](int kt, int st) {
        const int k0 = kt << 6;
        constexpr int GA = BM * 8 / THREADS;
#pragma unroll
        for (int i = 0; i < GA; i++) {
            int c = tid + i * THREADS;
            int row = c >> 3, g = c & 7;
            cp16(sA + st * BM * 64 + row * 64 + ((g ^ (row & 7)) << 3),
                 A + (size_t)(bm + row) * K + k0 + (g << 3));
        }
        constexpr int GB = 8 * BN / THREADS;
#pragma unroll
        for (int i = 0; i < GB; i++) {
            int c = tid + i * THREADS;
            int k = c / (BN / 8), g = c % (BN / 8);
            int blk = g >> 3, gg = (g & 7) ^ (k & 7);
            cp16(sB + st * 64 * BN + k * BN + blk * 64 + (gg << 3),
                 Bm + (size_t)(k0 + k) * N + bn + (g << 3));
        }
    };

    load_stage(0, 0); cp_commit();
    load_stage(1, 1); cp_commit();

    for (int kt = 0; kt < KT; kt++) {
        const int st = kt % STG;
        cp_wait1();
        __syncthreads();
        if (kt + 2 < KT) load_stage(kt + 2, (kt + 2) % STG);
        cp_commit();

        uint32_t baseA = (uint32_t)__cvta_generic_to_shared(sA + st * BM * 64);
        uint32_t baseB = (uint32_t)__cvta_generic_to_shared(sB + st * 64 * BN);

#pragma unroll
        for (int kk = 0; kk < 4; kk++) {
            uint32_t a[MF][4];
#pragma unroll
            for (int i = 0; i < MF; i++) {
                int row = wm + i * 16 + (l & 15);
                int g   = kk * 2 + (l >> 4);
                ldmx4(a[i], baseA + (uint32_t)(row * 64 + ((g ^ (row & 7)) << 3)) * 2);
            }
            uint32_t b[NF / 2][4];
#pragma unroll
            for (int j = 0; j < NF / 2; j++) {
                int k = kk * 16 + (l & 15);
                int g = ((wn + j * 16) >> 3) + (l >> 4);
                int blk = g >> 3, gg = (g & 7) ^ (k & 7);
                ldmx4t(b[j], baseB + (uint32_t)(k * BN + blk * 64 + (gg << 3)) * 2);
            }
#pragma unroll
            for (int i = 0; i < MF; i++)
#pragma unroll
                for (int j = 0; j < NF / 2; j++) {
                    mma16816(acc[i][2 * j],     a[i], b[j]);
                    mma16816(acc[i][2 * j + 1], a[i], b[j] + 2);
                }
        }
    }

    // ---- epilogue ----
    const int r  = l >> 2;
    const int c0 = (l & 3) * 2;
#pragma unroll
    for (int i = 0; i < MF; i++) {
        int m0 = bm + wm + i * 16;
#pragma unroll
        for (int j = 0; j < NF; j++) {
            int col = bn + wn + j * 8 + c0;
#pragma unroll
            for (int h = 0; h < 2; h++) {
                int m = m0 + r + h * 8;
                float2 val = make_float2(acc[i][j][2 * h], acc[i][j][2 * h + 1]);
                if (MODE == 0) {
                    *reinterpret_cast<float2*>(&C[(size_t)m * N + col]) = val;
                } else if (MODE == 1) {
                    float2* p = reinterpret_cast<float2*>(&C[(size_t)m * N + col]);
                    float2 o = *p;
                    o.x += val.x; o.y += val.y;
                    *p = o;
                } else {
                    float2 bb = *reinterpret_cast<const float2*>(&bias[col]);
                    val.x += bb.x; val.y += bb.y;
                    int t = m >> 6, b0 = m & 63;
                    *reinterpret_cast<float2*>(
                        &C[((size_t)b0 * TT + t) * OUTF + col]) = val;
                }
            }
        }
    }
}

// ---------------- conversion kernels -----------------------------------------
__global__ __launch_bounds__(256) void convx_kernel(const float* __restrict__ x,
                                                    __half* __restrict__ xh)
{
    int i  = blockIdx.x * 256 + threadIdx.x;
    int i4 = i % (INF / 4);
    int bt = i / (INF / 4);
    int b = bt / TT, t = bt % TT;
    float4 v = reinterpret_cast<const float4*>(x)[i];
    int dst = (t * BB + b) * (INF / 4) + i4;
    reinterpret_cast<__half2*>(xh)[2 * dst + 0] = __floats2half2_rn(v.x, v.y);
    reinterpret_cast<__half2*>(xh)[2 * dst + 1] = __floats2half2_rn(v.z, v.w);
}

__global__ __launch_bounds__(256) void f2h_kernel(const float* __restrict__ in,
                                                  __half* __restrict__ out)
{
    int i = blockIdx.x * 256 + threadIdx.x;
    float4 v = reinterpret_cast<const float4*>(in)[i];
    reinterpret_cast<__half2*>(out)[2 * i + 0] = __floats2half2_rn(v.x, v.y);
    reinterpret_cast<__half2*>(out)[2 * i + 1] = __floats2half2_rn(v.z, v.w);
}

__global__ void transp_kernel(const float* __restrict__ w, __half* __restrict__ wt)
{
    __shared__ float tile[32][33];
    int ox = blockIdx.x * 32, hy = blockIdx.y * 32;
    int tx = threadIdx.x, ty = threadIdx.y;
#pragma unroll
    for (int rr = 0; rr < 32; rr += 8)
        tile[ty + rr][tx] = w[(size_t)(ox + ty + rr) * HID + hy + tx];
    __syncthreads();
#pragma unroll
    for (int rr = 0; rr < 32; rr += 8)
        wt[(size_t)(hy + ty + rr) * OUTF + ox + tx] = __float2half(tile[tx][ty + rr]);
}

// ---------------- elementwise 20-step scan (exact R3) -------------------------
__device__ __forceinline__ float sigm(float x) { return 1.0f / (1.0f + __expf(-x)); }

__global__ __launch_bounds__(256) void scan_kernel(
    const float* __restrict__ syn_all,
    const float* __restrict__ trans_k_m,
    const float* __restrict__ trans_asc_k,
    const float* __restrict__ asc_amp,
    const float* __restrict__ trans_asc_r,
    const float* __restrict__ thresh,
    __half* __restrict__ firing,
    float* __restrict__ volt_st, float* __restrict__ asc_st,
    float* __restrict__ fire_st, int t0)
{
    int idx = blockIdx.x * blockDim.x + threadIdx.x;
    int h = idx & (HID - 1);

    float syn[DELAYS];
#pragma unroll
    for (int s = 0; s < DELAYS; s++)
        syn[s] = syn_all[(size_t)(t0 + s) * BH + idx];

    float km  = sigm(trans_k_m[h]);
    float c1  = 0.1f * km;
    float c2  = 1.0f - km;
    float ka0 = sigm(trans_asc_k[h]);
    float ka1 = sigm(trans_asc_k[HID + h]);
    float amp0 = asc_amp[h],       amp1 = asc_amp[HID + h];
    float r0 = 1.0f - 2.0f * sigm(trans_asc_r[h]);
    float r1 = 1.0f - 2.0f * sigm(trans_asc_r[HID + h]);
    float th = thresh[h];

    float f, v, a0, a1;
    if (t0 == 0) {
        f = 0.f; v = 0.f; a0 = 0.f; a1 = 0.f;
    } else {
        f  = fire_st[idx];
        v  = volt_st[idx];
        a0 = asc_st[idx];
        a1 = asc_st[BH + idx];
    }

#pragma unroll
    for (int s = 0; s < DELAYS; s++) {
        a0 = (amp0 + r0 * a0) * f * ka0 + (1.0f - ka0) * a0;
        a1 = (amp1 + r1 * a1) * f * ka1 + (1.0f - ka1) * a1;
        v  = c1 * (syn[s] + a0 + a1) + c2 * v;
        f  = sigm(v - th);
        firing[(size_t)(t0 + s) * BH + idx] = __float2half(f);
    }
    fire_st[idx] = f;
    volt_st[idx] = v;
    asc_st[idx] = a0;
    asc_st[BH + idx] = a1;
}

// ---------------- launch ------------------------------------------------------
extern "C" void kernel_launch(void* const* d_in, const int* in_sizes, int n_in,
                              void* d_out, int out_size)
{
    const float* x           = (const float*)d_in[0];
    const float* W_in        = (const float*)d_in[1];
    const float* W_lat       = (const float*)d_in[2];
    const float* thresh      = (const float*)d_in[3];
    const float* trans_k_m   = (const float*)d_in[4];
    const float* trans_asc_k = (const float*)d_in[5];
    const float* asc_amp     = (const float*)d_in[6];
    const float* trans_asc_r = (const float*)d_in[7];
    const float* W_out       = (const float*)d_in[8];
    const float* b_out       = (const float*)d_in[9];
    float* out = (float*)d_out;

    __half *xh, *Win, *Wlat, *WoutT, *firing;
    float *syn, *volt, *asc, *fire;
    cudaGetSymbolAddress((void**)&xh,     g_xh);
    cudaGetSymbolAddress((void**)&Win,    g_Win);
    cudaGetSymbolAddress((void**)&Wlat,   g_Wlat);
    cudaGetSymbolAddress((void**)&WoutT,  g_WoutT);
    cudaGetSymbolAddress((void**)&syn,    g_syn);
    cudaGetSymbolAddress((void**)&firing, g_firing);
    cudaGetSymbolAddress((void**)&volt,   g_volt);
    cudaGetSymbolAddress((void**)&asc,    g_asc);
    cudaGetSymbolAddress((void**)&fire,   g_fire);

    const int SM_BIG = STG * (128 * 64 + 64 * 128) * 2;   // 98304
    const int SM_LAT = STG * (64 * 64 + 64 * 64) * 2;     // 49152
    cudaFuncSetAttribute(mgemm<128, 128, 4, 2, 0>,
                         cudaFuncAttributeMaxDynamicSharedMemorySize, SM_BIG);
    cudaFuncSetAttribute(mgemm<64, 64, 2, 2, 1>,
                         cudaFuncAttributeMaxDynamicSharedMemorySize, SM_LAT);
    cudaFuncSetAttribute(mgemm<128, 128, 4, 2, 2>,
                         cudaFuncAttributeMaxDynamicSharedMemorySize, SM_BIG);

    cudaStream_t s0 = 0, s1 = g_ctx.s1, s2 = g_ctx.s2;

    // ---- fork event FIRST (capture-legal fork of side streams) ----
    cudaEventRecord(g_ctx.e_fork, s0);

    // ---- s1: W_lat fp16 conversion (needed before first lateral) ----
    cudaStreamWaitEvent(s1, g_ctx.e_fork, 0);
    f2h_kernel<<<(HID * HID / 4) / 256, 256, 0, s1>>>(W_lat, Wlat);
    cudaEventRecord(g_ctx.e_wlat, s1);

    // ---- s2: W_out transpose (needed before readout) ----
    cudaStreamWaitEvent(s2, g_ctx.e_fork, 0);
    transp_kernel<<<dim3(OUTF / 32, HID / 32), dim3(32, 8), 0, s2>>>(W_out, WoutT);
    cudaEventRecord(g_ctx.e_trans, s2);

    // ---- main stream: strictly sequential heavy work (R3 schedule) ----
    convx_kernel<<<(BB * TT * INF / 4) / 256, 256, 0, s0>>>(x, xh);
    f2h_kernel<<<(INF * HID / 4) / 256, 256, 0, s0>>>(W_in, Win);
    mgemm<128, 128, 4, 2, 0><<<dim3(HID / 128, (BB * TT) / 128), 256, SM_BIG, s0>>>(
        xh, Win, syn, nullptr, BB * TT, HID, INF);
    cudaStreamWaitEvent(s0, g_ctx.e_wlat, 0);

    for (int blk = 0; blk < NBLK; blk++) {
        if (blk > 0) {
            mgemm<64, 64, 2, 2, 1><<<dim3(HID / 64, MBLK / 64), 128, SM_LAT, s0>>>(
                firing + (size_t)(blk - 1) * MBLK * HID, Wlat,
                syn + (size_t)blk * MBLK * HID, nullptr, MBLK, HID, HID);
        }
        scan_kernel<<<BH / 256, 256, 0, s0>>>(
            syn, trans_k_m, trans_asc_k, asc_amp, trans_asc_r, thresh,
            firing, volt, asc, fire, blk * DELAYS);
    }

    // ---- readout: single full GEMM with fused bias + permute ----
    cudaStreamWaitEvent(s0, g_ctx.e_trans, 0);
    mgemm<128, 128, 4, 2, 2><<<dim3(OUTF / 128, (BB * TT) / 128), 256, SM_BIG, s0>>>(
        firing, WoutT, out, b_out, BB * TT, OUTF, HID);
}